// round 15
// baseline (speedup 1.0000x reference)
#include <cuda_runtime.h>

// Problem constants
#define N_LEN   131072
#define B_ROWS  256

// Tiling: ONE WARP PER BLOCK; each warp owns a 512-position tile of a row-pair.
#define TPB     32
#define WTILE   512                    // positions per warp tile
#define EPT     16                     // positions per lane
#define W_IN    (WTILE + 32)           // 544 x-pairs incl 32-halo
#define W_PAD   ((W_IN / 16) * 18)     // 612 u64 slots (pad-18: even stride, 16B-aligned)

typedef unsigned long long u64;

__device__ __forceinline__ u64 pack2(float a, float b) {
    u64 r; asm("mov.b64 %0,{%1,%2};" : "=l"(r) : "f"(a), "f"(b)); return r;
}
__device__ __forceinline__ void unpack2(u64 v, float& a, float& b) {
    asm("mov.b64 {%0,%1},%2;" : "=f"(a), "=f"(b) : "l"(v));
}
__device__ __forceinline__ u64 fma2(u64 a, u64 b, u64 c) {
    u64 d; asm("fma.rn.f32x2 %0,%1,%2,%3;" : "=l"(d) : "l"(a), "l"(b), "l"(c)); return d;
}
__device__ __forceinline__ u64 mul2(u64 a, u64 b) {
    u64 d; asm("mul.rn.f32x2 %0,%1,%2;" : "=l"(d) : "l"(a), "l"(b)); return d;
}
__device__ __forceinline__ u64 add2(u64 a, u64 b) {
    u64 d; asm("add.rn.f32x2 %0,%1,%2;" : "=l"(d) : "l"(a), "l"(b)); return d;
}

// pad-18-per-16 swizzle: lane stride 18 slots = 36 words == 4 mod 32 ->
// 8-lane LDS.128 wavefronts hit distinct 4-word bank groups (conflict-free),
// and all lane bases are even -> 16B alignment for 128-bit smem ops.
__device__ __forceinline__ int sw(int k) { return (k >> 4) * 18 + (k & 15); }

__global__ void __launch_bounds__(TPB, 16) fir2(const float* __restrict__ x,
                                                const float* __restrict__ h,
                                                float* __restrict__ y) {
    __shared__ __align__(16) u64 sIn[W_PAD];   // x window; reused for y staging
    __shared__ u64 sHv[16];                    // tile-boundary v halo

    const int lane = threadIdx.x;
    const int pair = blockIdx.y;
    const int c0   = blockIdx.x * WTILE;               // warp tile base
    const float* __restrict__ x0 = x + (size_t)(2 * pair) * N_LEN;
    const float* __restrict__ x1 = x0 + N_LEN;
    float* __restrict__ y0 = y + (size_t)(2 * pair) * N_LEN;
    float* __restrict__ y1 = y0 + N_LEN;

    // 16 packed coefficients via 4x LDG.128; pass 2 indexes reversed as h[15-j]
    u64 gph[16];
    {
        const float4* h4 = reinterpret_cast<const float4*>(h);
#pragma unroll
        for (int q = 0; q < 4; q++) {
            float4 hv = __ldg(h4 + q);
            gph[4 * q + 0] = pack2(hv.x, hv.x);
            gph[4 * q + 1] = pack2(hv.y, hv.y);
            gph[4 * q + 2] = pack2(hv.z, hv.z);
            gph[4 * q + 3] = pack2(hv.w, hv.w);
        }
    }

    // ---- stage x: LDG.128 both rows -> 2x STS.128 (pair-interleaved float4) ----
#pragma unroll
    for (int it = 0; it < 5; it++) {
        int g = lane + it * 32;        // float4 group, 136 groups of 4 pairs
        if (g < W_IN / 4) {
            int p = c0 - 32 + 4 * g;   // 16B-aligned; <0 only for the first tile
            float4 a0, a1;
            if (p >= 0) {
                a0 = *reinterpret_cast<const float4*>(x0 + p);
                a1 = *reinterpret_cast<const float4*>(x1 + p);
            } else {
                a0 = make_float4(0.f, 0.f, 0.f, 0.f);
                a1 = make_float4(0.f, 0.f, 0.f, 0.f);
            }
            int s0 = sw(4 * g);        // even slot -> 16B aligned
            *reinterpret_cast<float4*>(&sIn[s0])     = make_float4(a0.x, a1.x, a0.y, a1.y);
            *reinterpret_cast<float4*>(&sIn[s0 + 2]) = make_float4(a0.z, a1.z, a0.w, a1.w);
        }
    }
    __syncwarp(0xffffffffu);

    const bool kill = (c0 == 0) && (lane == 0);        // positions 0..15 masked to 0

    // ---- pass 1: v[p] = x[p] + sum_{j=0..15} h[j]*x[p-1-j] ----
    // xi[0..15] loaded up front (8 pipelined LDS.128); ring r from shfl of the
    // previous lane's xi (zero L1 traffic); all tap indices compile-time.
    u64 vbuf[16];
    {
        u64 xi[16];
        const int xA = 18 * (lane + 2);                // slots xA+t = x[c0+lo+t]
#pragma unroll
        for (int m = 0; m < 8; m++) {
            ulonglong2 X = *reinterpret_cast<const ulonglong2*>(&sIn[xA + 2 * m]);
            xi[2 * m] = X.x; xi[2 * m + 1] = X.y;
        }

        u64 r[16];                                     // r[s] = x[c0+lo-16+s]
#pragma unroll
        for (int s = 0; s < 16; s++)
            r[s] = __shfl_up_sync(0xffffffffu, xi[s], 1);
        if (lane == 0) {                               // from staged halo slots
#pragma unroll
            for (int s = 0; s < 16; s++) r[s] = sIn[sw(16 + s)];
        }

#pragma unroll
        for (int t = 0; t < EPT; t++) {
            u64 acc0 = xi[t];
#pragma unroll
            for (int j = 0; j < 8; j++) {
                int k = t - 1 - j;
                u64 tap = (k >= 0) ? xi[k] : r[16 + k];
                acc0 = fma2(gph[j], tap, acc0);
            }
            u64 tap8;
            { int k = t - 9; tap8 = (k >= 0) ? xi[k] : r[16 + k]; }
            u64 acc1 = mul2(gph[8], tap8);
#pragma unroll
            for (int j = 9; j < 16; j++) {
                int k = t - 1 - j;
                u64 tap = (k >= 0) ? xi[k] : r[16 + k];
                acc1 = fma2(gph[j], tap, acc1);
            }
            vbuf[t] = add2(acc0, acc1);
        }
    }
    if (kill) {
#pragma unroll
        for (int t = 0; t < EPT; t++) vbuf[t] = 0ULL;
    }

    // ---- tile-boundary v halo: v[c0-16+s] recomputed from x (lanes 0..15) ----
    if (lane < 16) {
        u64 v = 0ULL;
        if (c0 - 16 + lane >= 16) {                    // pos>=16 -> unmasked
            u64 xi = sIn[sw(16 + lane)];               // x[c0-16+lane]
            u64 a0 = xi;
#pragma unroll
            for (int j = 0; j < 8; j++)  a0 = fma2(gph[j], sIn[sw(15 + lane - j)], a0);
            u64 a1 = mul2(gph[8], sIn[sw(7 + lane)]);
#pragma unroll
            for (int j = 9; j < 16; j++) a1 = fma2(gph[j], sIn[sw(15 + lane - j)], a1);
            v = add2(a0, a1);
        }
        sHv[lane] = v;
    }
    __syncwarp(0xffffffffu);           // sHv visible; all x reads done before y overwrites

    // ---- pass 2: y[p] = v[p] + sum_j h[15-j]*v[p-1-j]; halo via shfl ----
    {
        u64 hv[16];                    // v[lo-16+s]: previous lane's vbuf
#pragma unroll
        for (int s = 0; s < 16; s++)
            hv[s] = __shfl_up_sync(0xffffffffu, vbuf[s], 1);
        if (lane == 0) {
#pragma unroll
            for (int s = 0; s < 16; s++) hv[s] = sHv[s];
        }

        const int yA = 18 * lane;      // slot sw(lo+t) = 18*lane + t (even base)
        u64 ysave = 0ULL;
#pragma unroll
        for (int t = 0; t < EPT; t++) {
            u64 acc0 = vbuf[t];
#pragma unroll
            for (int j = 0; j < 8; j++) {
                int k = t - 1 - j;
                u64 tap = (k >= 0) ? vbuf[k] : hv[16 + k];
                acc0 = fma2(gph[15 - j], tap, acc0);
            }
            u64 tap8;
            { int k = t - 9; tap8 = (k >= 0) ? vbuf[k] : hv[16 + k]; }
            u64 acc1 = mul2(gph[7], tap8);
#pragma unroll
            for (int j = 9; j < 16; j++) {
                int k = t - 1 - j;
                u64 tap = (k >= 0) ? vbuf[k] : hv[16 + k];
                acc1 = fma2(gph[15 - j], tap, acc1);
            }
            u64 yv = add2(acc0, acc1);
            if (kill) yv = 0ULL;       // positions 0..15 masked
            if (t & 1) {               // paired STS.128 (16B-aligned even base)
                ulonglong2 w; w.x = ysave; w.y = yv;
                *reinterpret_cast<ulonglong2*>(&sIn[yA + t - 1]) = w;
            } else {
                ysave = yv;
            }
        }
    }
    __syncwarp(0xffffffffu);           // y staged

    // ---- writeout: LDS.128 gathers + coalesced STG.128 per row ----
#pragma unroll
    for (int it = 0; it < 4; it++) {
        int fi = 4 * (lane + it * 32); // 4-pair group
        int ix = sw(fi);               // even slot, 16B aligned
        ulonglong2 p0 = *reinterpret_cast<const ulonglong2*>(&sIn[ix]);
        ulonglong2 p1 = *reinterpret_cast<const ulonglong2*>(&sIn[ix + 2]);
        float a[4], b[4];
        unpack2(p0.x, a[0], b[0]); unpack2(p0.y, a[1], b[1]);
        unpack2(p1.x, a[2], b[2]); unpack2(p1.y, a[3], b[3]);
        *reinterpret_cast<float4*>(y0 + c0 + fi) = make_float4(a[0], a[1], a[2], a[3]);
        *reinterpret_cast<float4*>(y1 + c0 + fi) = make_float4(b[0], b[1], b[2], b[3]);
    }
}

extern "C" void kernel_launch(void* const* d_in, const int* in_sizes, int n_in,
                              void* d_out, int out_size) {
    (void)in_sizes; (void)n_in; (void)out_size;
    const float* x = (const float*)d_in[0];
    const float* h = (const float*)d_in[1];
    float* y = (float*)d_out;

    dim3 grid(N_LEN / WTILE, B_ROWS / 2, 1);
    fir2<<<grid, TPB>>>(x, h, y);
}